// round 13
// baseline (speedup 1.0000x reference)
#include <cuda_runtime.h>

#define TSTEPS 2048
#define BSIZE  8192
#define HH     0.01f
#define NG     (TSTEPS / 4)   // 512 groups of 4 steps
#define PD     4              // prefetch distance (groups)

typedef unsigned long long u64;

__device__ __forceinline__ float ex2f(float x) {
    float y; asm("ex2.approx.ftz.f32 %0, %1;" : "=f"(y) : "f"(x)); return y;
}
__device__ __forceinline__ float rcpf(float x) {
    float y; asm("rcp.approx.ftz.f32 %0, %1;" : "=f"(y) : "f"(x)); return y;
}
__device__ __forceinline__ u64 pk(float lo, float hi) {
    u64 r; asm("mov.b64 %0, {%1, %2};" : "=l"(r) : "f"(lo), "f"(hi)); return r;
}
__device__ __forceinline__ void upk(float& lo, float& hi, u64 v) {
    asm("mov.b64 {%0, %1}, %2;" : "=f"(lo), "=f"(hi) : "l"(v));
}
__device__ __forceinline__ u64 fma2(u64 a, u64 b, u64 c) {
    u64 d; asm("fma.rn.f32x2 %0, %1, %2, %3;" : "=l"(d) : "l"(a), "l"(b), "l"(c)); return d;
}
__device__ __forceinline__ u64 add2(u64 a, u64 b) {
    u64 d; asm("add.rn.f32x2 %0, %1, %2;" : "=l"(d) : "l"(a), "l"(b)); return d;
}

struct CP {
    u64 E2, HH2, Cp;                       // packed linear-dynamics constants
    float a11, a12, a13, a14, a22, a23, a24, a33, a34, a44;  // -log2e * symm L
    float bm1, bm2, bm3, bm4, bm0;                           // -log2e * M, Mo
    float K1, K2;
};

// One step. delta = sigmoid(phi) = rcp(1 + ex2(phiS)), phiS loop-carried.
// Packed geometry (BASE, accQ) + scalar balanced tree (short chain).
// Chain: ex2(16) -> +1(4) -> rcp(16) -> u(4) -> x(4) -> tree(~20) = ~60 cyc.
// fma-pipe issues ~31 -> slot floor ~62. Balanced by design.
template<bool ADDSC>
__device__ __forceinline__ void stepP(const CP& c, float w1, float w2,
                                      u64& X, float& h1, float& h2,
                                      float& phiS, u64& accQ2, float& accR,
                                      float& accT)
{
    float e = ex2f(phiS);                     // MUFU #1, issues first

    // ---- pre-delta work, fills both MUFU shadows ----
    float x1, x2; upk(x1, x2, X);
    float dx1 = x1 - h1, dx2 = x2 - h2;
    float kuh = fmaf(c.K2, h2, c.K1 * h1);    // K . x_hat
    float kdx = fmaf(c.K2, dx2, c.K1 * dx1);  // K . (x - x_hat)

    u64 W  = pk(w1, w2);
    u64 WC = add2(W, c.Cp);                   // w + (h^2/2, -h^2)
    u64 T1 = fma2(X, c.E2, WC);               // + 0.98 * x
    u64 Xs = pk(x2, x1);
    u64 BASE = fma2(Xs, c.HH2, T1);           // + 0.01 * x_swapped
    float b1, b2; upk(b1, b2, BASE);

    if (ADDSC) {
        accQ2 = fma2(X, X, accQ2);            // packed sum of x^2
        float kx = kuh + kdx;                 // u_s = K . x (exact)
        accR = fmaf(kx, kx, accR);            // 0.1 applied once at the end
    }

    float den   = 1.0f + e;
    float delta = rcpf(den);                  // MUFU #2
    if (ADDSC) accT = accT + delta;           // off the chain

    // ---- post-rcp: u-form scalar updates ----
    float u = fmaf(delta, kdx, kuh);          // K . x_hat_new
    float nx1 = fmaf(HH, u, b1);
    float nx2 = fmaf(HH, u, b2);
    h1 = fmaf(delta, dx1, h1);                // ready at delta+4
    h2 = fmaf(delta, dx2, h2);
    X = pk(nx1, nx2);                         // repack for next iteration

    // ---- scalar balanced tree for the NEXT phiS (14 fma, depth ~20) ----
    // h-driven q's are ready first; r-chain consumes in readiness order.
    float q4 = fmaf(c.a44, h2, c.bm4);
    float q3 = fmaf(c.a33, h1, fmaf(c.a34, h2, c.bm3));
    float q2 = fmaf(c.a22, nx2, fmaf(c.a23, h1, fmaf(c.a24, h2, c.bm2)));
    float q1 = fmaf(c.a11, nx1, fmaf(c.a12, nx2,
               fmaf(c.a13, h1, fmaf(c.a14, h2, c.bm1))));
    float r  = fmaf(h2, q4, c.bm0);
    r        = fmaf(h1, q3, r);
    r        = fmaf(nx2, q2, r);
    phiS     = fmaf(nx1, q1, r);
}

__global__ void __launch_bounds__(64, 1) cstr_traj_kernel(
    const float* __restrict__ w,   // (B, 2, T)
    const float* __restrict__ K,   // (1, 2)
    const float* __restrict__ L,   // (4, 4)
    const float* __restrict__ M,   // (1, 4)
    const float* __restrict__ Mo,  // (1, 1)
    float* __restrict__ out)       // (B,)
{
    int b = blockIdx.x * blockDim.x + threadIdx.x;

    const float s = -1.44269504088896340736f;  // -log2(e), folded into phi
    CP c;
    c.K1 = __ldg(K);  c.K2 = __ldg(K + 1);
    float l[16];
#pragma unroll
    for (int i = 0; i < 16; i++) l[i] = __ldg(L + i);
    c.a11 = s * l[0];           c.a22 = s * l[5];
    c.a33 = s * l[10];          c.a44 = s * l[15];
    c.a12 = s * (l[1] + l[4]);  c.a13 = s * (l[2] + l[8]);
    c.a14 = s * (l[3] + l[12]); c.a23 = s * (l[6] + l[9]);
    c.a24 = s * (l[7] + l[13]); c.a34 = s * (l[11] + l[14]);
    c.bm1 = s * __ldg(M);       c.bm2 = s * __ldg(M + 1);
    c.bm3 = s * __ldg(M + 2);   c.bm4 = s * __ldg(M + 3);
    c.bm0 = s * __ldg(Mo);
    c.E2  = pk(0.98f, 0.98f);
    c.HH2 = pk(HH, HH);
    c.Cp  = pk(0.5f * HH * HH, -HH * HH);      // (+h^2/2, -h^2)

    const float4* w0 = (const float4*)(w + (size_t)b * 2 * TSTEPS);
    const float4* w1 = (const float4*)(w + (size_t)b * 2 * TSTEPS + TSTEPS);

    u64 X = pk(1.0f, 0.0f);
    float h1 = 1.0f, h2 = 0.0f;
    u64 accQ2 = pk(0.0f, 0.0f);
    float accR = 0.0f, accT = 0.0f;
    // Step 0: reference forces delta=1 with x_hat frozen. dx==0 makes delta
    // inert in the dynamics; phiS=-200 -> ex2 flushes to 0 -> delta=rcp(1)=1
    // EXACTLY, so accT gets exactly 1.0. No special case needed.
    float phiS = -200.0f;

    // ---- software prefetch pipeline: PD groups in registers ----
    float4 bA[PD], bB[PD];
#pragma unroll
    for (int d = 0; d < PD; ++d) { bA[d] = w0[d]; bB[d] = w1[d]; }

    // First PD groups (consume slot d, prefetch group PD+d)
#pragma unroll
    for (int d = 0; d < PD; ++d) {
        float4 wa = bA[d], wb = bB[d];
        bA[d] = w0[PD + d]; bB[d] = w1[PD + d];
        stepP<true>(c, wa.x, wb.x, X, h1, h2, phiS, accQ2, accR, accT);
        stepP<true>(c, wa.y, wb.y, X, h1, h2, phiS, accQ2, accR, accT);
        stepP<true>(c, wa.z, wb.z, X, h1, h2, phiS, accQ2, accR, accT);
        stepP<true>(c, wa.w, wb.w, X, h1, h2, phiS, accQ2, accR, accT);
    }

    // Main: consume slot d = group base+d, prefetch group base+PD+d
    for (int base = PD; base < NG - PD; base += PD) {
#pragma unroll
        for (int d = 0; d < PD; ++d) {
            float4 wa = bA[d], wb = bB[d];
            bA[d] = w0[base + PD + d];
            bB[d] = w1[base + PD + d];
            stepP<true>(c, wa.x, wb.x, X, h1, h2, phiS, accQ2, accR, accT);
            stepP<true>(c, wa.y, wb.y, X, h1, h2, phiS, accQ2, accR, accT);
            stepP<true>(c, wa.z, wb.z, X, h1, h2, phiS, accQ2, accR, accT);
            stepP<true>(c, wa.w, wb.w, X, h1, h2, phiS, accQ2, accR, accT);
        }
    }

    // Tail: groups NG-PD .. NG-1 from the buffers (static slots)
#pragma unroll
    for (int d = 0; d < PD - 1; ++d) {
        float4 wa = bA[d], wb = bB[d];
        stepP<true>(c, wa.x, wb.x, X, h1, h2, phiS, accQ2, accR, accT);
        stepP<true>(c, wa.y, wb.y, X, h1, h2, phiS, accQ2, accR, accT);
        stepP<true>(c, wa.z, wb.z, X, h1, h2, phiS, accQ2, accR, accT);
        stepP<true>(c, wa.w, wb.w, X, h1, h2, phiS, accQ2, accR, accT);
    }
    {   // last group: final step (i = T-1) updates state, adds no stage cost
        float4 wa = bA[PD - 1], wb = bB[PD - 1];
        stepP<true >(c, wa.x, wb.x, X, h1, h2, phiS, accQ2, accR, accT);
        stepP<true >(c, wa.y, wb.y, X, h1, h2, phiS, accQ2, accR, accT);
        stepP<true >(c, wa.z, wb.z, X, h1, h2, phiS, accQ2, accR, accT);
        stepP<false>(c, wa.w, wb.w, X, h1, h2, phiS, accQ2, accR, accT);
    }

    // J = Sigma x^T x + 0.1 Sigma u_s^2 + Sigma delta + terminal 10|x_T|^2
    float aq1, aq2; upk(aq1, aq2, accQ2);
    float J = aq1 + aq2;
    J = fmaf(0.1f, accR, J);
    J = J + accT;
    float x1, x2; upk(x1, x2, X);
    J = fmaf(10.0f * x1, x1, J);
    J = fmaf(10.0f * x2, x2, J);

    if (b < BSIZE) out[b] = J;
}

extern "C" void kernel_launch(void* const* d_in, const int* in_sizes, int n_in,
                              void* d_out, int out_size)
{
    const float* w  = (const float*)d_in[0];
    const float* K  = (const float*)d_in[1];
    const float* L  = (const float*)d_in[2];
    const float* M  = (const float*)d_in[3];
    const float* Mo = (const float*)d_in[4];
    float* out = (float*)d_out;

    // 8192 trajectories, 1 thread each; 128 blocks x 64 threads = 256 warps,
    // one warp per SMSP.
    cstr_traj_kernel<<<BSIZE / 64, 64>>>(w, K, L, M, Mo, out);
}

// round 14
// speedup vs baseline: 1.4094x; 1.4094x over previous
#include <cuda_runtime.h>

#define TSTEPS 2048
#define BSIZE  8192
#define HH     0.01f
#define NG     (TSTEPS / 4)   // 512 groups of 4 steps
#define PD     4              // prefetch distance (groups)

typedef unsigned long long u64;

__device__ __forceinline__ float ex2f(float x) {
    float y; asm("ex2.approx.ftz.f32 %0, %1;" : "=f"(y) : "f"(x)); return y;
}
__device__ __forceinline__ float rcpf(float x) {
    float y; asm("rcp.approx.ftz.f32 %0, %1;" : "=f"(y) : "f"(x)); return y;
}
__device__ __forceinline__ u64 pk(float lo, float hi) {
    u64 r; asm("mov.b64 %0, {%1, %2};" : "=l"(r) : "f"(lo), "f"(hi)); return r;
}
__device__ __forceinline__ void upk(float& lo, float& hi, u64 v) {
    asm("mov.b64 {%0, %1}, %2;" : "=f"(lo), "=f"(hi) : "l"(v));
}
__device__ __forceinline__ u64 fma2(u64 a, u64 b, u64 c) {
    u64 d; asm("fma.rn.f32x2 %0, %1, %2, %3;" : "=l"(d) : "l"(a), "l"(b), "l"(c)); return d;
}
__device__ __forceinline__ u64 add2(u64 a, u64 b) {
    u64 d; asm("add.rn.f32x2 %0, %1, %2;" : "=l"(d) : "l"(a), "l"(b)); return d;
}
__device__ __forceinline__ u64 mul2(u64 a, u64 b) {
    u64 d; asm("mul.rn.f32x2 %0, %1, %2;" : "=l"(d) : "l"(a), "l"(b)); return d;
}

struct CP {
    u64 NEG1, E2, HH2, HHb, Cp;
    // phi tree, lane-matched coefficient pairs (coeffs scaled by -log2e):
    //   Q12 = X*(a11,a22) + Xs*(a12,0) + Hh*(a13,a24) + Hs*(a14,a23) + (bm1,bm2)
    //   Q34 = Hh*(a33,a44) + Hs*(a34,0) + (bm3,bm4)
    //   PP  = X*Q12 + (Hh*Q34 + (bm0,0));  phiS = PP.lo + PP.hi
    u64 CA, CB, CC, CD, Bm12, CE, CF, Bm34, Cbm0;
    float K1, K2;
};

// One step. delta = sigmoid(phi) = rcp(1 + ex2(phiS)), phiS loop-carried as a
// SCALAR (horizontal reduce done at the tail of the producing step).
// Chain: ex2(16) -> +1(4) -> rcp(16) -> bcast(~2) -> fma(4) ->
//        balanced tree(~18) -> horizontal(~6).
template<bool ADDSC>
__device__ __forceinline__ void stepP(const CP& c, float w1, float w2,
                                      u64& X, u64& Hh, float& phiS,
                                      u64& accQ2, float& accR, float& accT)
{
    float e = ex2f(phiS);                     // MUFU #1, issues first

    // ---- pre-delta geometry (fills both MUFU shadows) ----
    u64 DX = fma2(Hh, c.NEG1, X);             // (dx1, dx2) = X - H
    float dx1, dx2; upk(dx1, dx2, DX);
    float h1, h2;   upk(h1, h2, Hh);
    float x1s, x2s; upk(x1s, x2s, X);
    u64 Xs = pk(x2s, x1s);                    // swapped pair

    float kuh = fmaf(c.K2, h2, c.K1 * h1);    // K . x_hat
    float kdx = fmaf(c.K2, dx2, c.K1 * dx1);  // K . (x - x_hat)
    float hkdx = 0.01f * kdx;                 // delta-coefficient of x'

    u64 W  = pk(w1, w2);
    u64 WC = add2(W, c.Cp);                   // + (h^2/2, -h^2)
    u64 T1 = fma2(X, c.E2, WC);               // 0.98*x + w + C
    u64 BASE = fma2(Xs, c.HH2, T1);           // + 0.01*x_swapped
    u64 KUH2 = pk(kuh, kuh);
    u64 BXu  = fma2(KUH2, c.HHb, BASE);       // + HH*kuh (both lanes)
    u64 HKp  = pk(hkdx, hkdx);

    if (ADDSC) {
        accQ2 = fma2(X, X, accQ2);            // packed sum of x^2
        float kx = kuh + kdx;                 // u_s = K . x (exact)
        accR = fmaf(kx, kx, accR);            // 0.1 applied once at the end
    }

    float den   = 1.0f + e;
    float delta = rcpf(den);                  // MUFU #2
    if (ADDSC) accT = accT + delta;           // LAM * delta, off the chain

    // ---- post-rcp: broadcast + one packed FMA per state pair ----
    u64 DEL2 = pk(delta, delta);
    X  = fma2(DEL2, HKp, BXu);
    Hh = fma2(DEL2, DX, Hh);

    // ---- balanced phiS tree for the NEXT step ----
    float x1, x2; upk(x1, x2, X);
    float g1, g2; upk(g1, g2, Hh);
    u64 Xs2 = pk(x2, x1);
    u64 Hs2 = pk(g2, g1);
    // Two parallel halves (each depth 8 from state-ready), joined by add2:
    u64 QA  = fma2(X,   c.CA, fma2(Xs2, c.CB, c.Bm12));
    u64 QB  = fma2(Hh,  c.CC, mul2(Hs2, c.CD));
    u64 Q12 = add2(QA, QB);
    u64 Q34 = fma2(Hh, c.CE, fma2(Hs2, c.CF, c.Bm34));
    // Late Q12 in the OUTER slot; inner fma2 issues while Q12 finishes.
    u64 PP  = fma2(X, Q12, fma2(Hh, Q34, c.Cbm0));
    float plo, phi_; upk(plo, phi_, PP);
    phiS = plo + phi_;                        // scalar carried into next step
}

__global__ void __launch_bounds__(64, 1) cstr_traj_kernel(
    const float* __restrict__ w,   // (B, 2, T)
    const float* __restrict__ K,   // (1, 2)
    const float* __restrict__ L,   // (4, 4)
    const float* __restrict__ M,   // (1, 4)
    const float* __restrict__ Mo,  // (1, 1)
    float* __restrict__ out)       // (B,)
{
    int b = blockIdx.x * blockDim.x + threadIdx.x;

    const float s = -1.44269504088896340736f;  // -log2(e), folded into phi
    float K1 = __ldg(K), K2 = __ldg(K + 1);
    float l[16];
#pragma unroll
    for (int i = 0; i < 16; i++) l[i] = __ldg(L + i);
    float a11 = s * l[0],           a22 = s * l[5];
    float a33 = s * l[10],          a44 = s * l[15];
    float a12 = s * (l[1] + l[4]),  a13 = s * (l[2] + l[8]);
    float a14 = s * (l[3] + l[12]), a23 = s * (l[6] + l[9]);
    float a24 = s * (l[7] + l[13]), a34 = s * (l[11] + l[14]);
    float bm1 = s * __ldg(M),       bm2 = s * __ldg(M + 1);
    float bm3 = s * __ldg(M + 2),   bm4 = s * __ldg(M + 3);
    float bm0 = s * __ldg(Mo);

    CP c;
    c.K1 = K1; c.K2 = K2;
    c.NEG1 = pk(-1.0f, -1.0f);
    c.E2   = pk(0.98f, 0.98f);
    c.HH2  = pk(HH, HH);
    c.HHb  = pk(HH, HH);
    c.Cp   = pk(0.5f * HH * HH, -HH * HH);      // (+h^2/2, -h^2)
    // Lane check (q1,q2): q1 = a11 x1 + a12 x2 + a13 h1 + a14 h2 + bm1
    //                     q2 = a22 x2 +   0 x1 + a24 h2 + a23 h1 + bm2
    c.CA = pk(a11, a22);    // * X  = (x1, x2)
    c.CB = pk(a12, 0.0f);   // * Xs = (x2, x1)
    c.CC = pk(a13, a24);    // * Hh = (h1, h2)
    c.CD = pk(a14, a23);    // * Hs = (h2, h1)
    c.Bm12 = pk(bm1, bm2);
    // (q3,q4): q3 = a33 h1 + a34 h2 + bm3 ; q4 = a44 h2 + 0 h1 + bm4
    c.CE = pk(a33, a44);    // * Hh
    c.CF = pk(a34, 0.0f);   // * Hs
    c.Bm34 = pk(bm3, bm4);
    c.Cbm0 = pk(bm0, 0.0f);

    const float4* w0 = (const float4*)(w + (size_t)b * 2 * TSTEPS);
    const float4* w1 = (const float4*)(w + (size_t)b * 2 * TSTEPS + TSTEPS);

    u64 X  = pk(1.0f, 0.0f);
    u64 Hh = pk(1.0f, 0.0f);
    u64 accQ2 = pk(0.0f, 0.0f);
    float accR = 0.0f, accT = 0.0f;
    // Step 0: reference forces delta=1 with x_hat frozen. dx==0 makes delta
    // inert in the dynamics; phiS=-200 -> ex2 flushes to 0 -> delta=rcp(1)=1
    // EXACTLY, so accT gets exactly 1.0. No special case, no reconstruction.
    float phiS = -200.0f;

    // ---- software prefetch pipeline: PD groups in registers ----
    float4 bA[PD], bB[PD];
#pragma unroll
    for (int d = 0; d < PD; ++d) { bA[d] = w0[d]; bB[d] = w1[d]; }

    // First PD groups (consume slot d, prefetch group PD+d)
#pragma unroll
    for (int d = 0; d < PD; ++d) {
        float4 wa = bA[d], wb = bB[d];
        bA[d] = w0[PD + d]; bB[d] = w1[PD + d];
        stepP<true>(c, wa.x, wb.x, X, Hh, phiS, accQ2, accR, accT);
        stepP<true>(c, wa.y, wb.y, X, Hh, phiS, accQ2, accR, accT);
        stepP<true>(c, wa.z, wb.z, X, Hh, phiS, accQ2, accR, accT);
        stepP<true>(c, wa.w, wb.w, X, Hh, phiS, accQ2, accR, accT);
    }

    // Main: consume slot d = group base+d, prefetch group base+PD+d
    for (int base = PD; base < NG - PD; base += PD) {
#pragma unroll
        for (int d = 0; d < PD; ++d) {
            float4 wa = bA[d], wb = bB[d];
            bA[d] = w0[base + PD + d];
            bB[d] = w1[base + PD + d];
            stepP<true>(c, wa.x, wb.x, X, Hh, phiS, accQ2, accR, accT);
            stepP<true>(c, wa.y, wb.y, X, Hh, phiS, accQ2, accR, accT);
            stepP<true>(c, wa.z, wb.z, X, Hh, phiS, accQ2, accR, accT);
            stepP<true>(c, wa.w, wb.w, X, Hh, phiS, accQ2, accR, accT);
        }
    }

    // Tail: groups NG-PD .. NG-1 from the buffers (static slots)
#pragma unroll
    for (int d = 0; d < PD - 1; ++d) {
        float4 wa = bA[d], wb = bB[d];
        stepP<true>(c, wa.x, wb.x, X, Hh, phiS, accQ2, accR, accT);
        stepP<true>(c, wa.y, wb.y, X, Hh, phiS, accQ2, accR, accT);
        stepP<true>(c, wa.z, wb.z, X, Hh, phiS, accQ2, accR, accT);
        stepP<true>(c, wa.w, wb.w, X, Hh, phiS, accQ2, accR, accT);
    }
    {   // last group: final step (i = T-1) updates state, adds no stage cost
        float4 wa = bA[PD - 1], wb = bB[PD - 1];
        stepP<true >(c, wa.x, wb.x, X, Hh, phiS, accQ2, accR, accT);
        stepP<true >(c, wa.y, wb.y, X, Hh, phiS, accQ2, accR, accT);
        stepP<true >(c, wa.z, wb.z, X, Hh, phiS, accQ2, accR, accT);
        stepP<false>(c, wa.w, wb.w, X, Hh, phiS, accQ2, accR, accT);
    }

    // J = Sigma x^T x + 0.1 Sigma u_s^2 + Sigma delta + terminal 10|x_T|^2
    float aq1, aq2; upk(aq1, aq2, accQ2);
    float J = aq1 + aq2;
    J = fmaf(0.1f, accR, J);
    J = J + accT;
    float x1, x2; upk(x1, x2, X);
    J = fmaf(10.0f * x1, x1, J);
    J = fmaf(10.0f * x2, x2, J);

    if (b < BSIZE) out[b] = J;
}

extern "C" void kernel_launch(void* const* d_in, const int* in_sizes, int n_in,
                              void* d_out, int out_size)
{
    const float* w  = (const float*)d_in[0];
    const float* K  = (const float*)d_in[1];
    const float* L  = (const float*)d_in[2];
    const float* M  = (const float*)d_in[3];
    const float* Mo = (const float*)d_in[4];
    float* out = (float*)d_out;

    // 8192 trajectories, 1 thread each; 128 blocks x 64 threads = 256 warps,
    // one warp per SMSP.
    cstr_traj_kernel<<<BSIZE / 64, 64>>>(w, K, L, M, Mo, out);
}